// round 10
// baseline (speedup 1.0000x reference)
#include <cuda_runtime.h>

#define MAX_V 50000
#define MAX_E 200000

// Scratch (device globals — no allocation allowed in kernel_launch).
// 3 rotating var-belief buffers: at step k, read (k+2)%3, write k%3, and
// refill (k+1)%3 with unary for step k+1 (its last reader was step k-1).
__device__ __align__(16) float g_vb[3][MAX_V * 8];
// Messages, interleaved per 4-lane layout: edge e, lane l (states 2l,2l+1)
// holds float4 {m0[2l], m0[2l+1], m1[2l], m1[2l+1]} at g_msg[e*16 + l*4].
__device__ __align__(16) float g_msg[MAX_E * 16];
// int16-quantized pairwise (scale 4096): halves the dominant stream.
__device__ __align__(16) short g_pw16[MAX_E * 64];

#define Q_SCALE 4096.0f
#define Q_INV   2.44140625e-4f

__device__ __forceinline__ float neg_inf() { return __int_as_float(0xff800000); }

// Streaming store (outputs: written once, never re-read — don't pollute L2).
__device__ __forceinline__ void stg_cs4(float* p, float4 v) {
    asm volatile("st.global.cs.v4.f32 [%0], {%1,%2,%3,%4};"
                 :: "l"(p), "f"(v.x), "f"(v.y), "f"(v.z), "f"(v.w));
}
// Vector float2 reduction (sm_90+): one RED issue for two states.
__device__ __forceinline__ void red_add_v2(float* p, float a, float b) {
    asm volatile("red.global.add.v2.f32 [%0], {%1, %2};"
                 :: "l"(p), "f"(a), "f"(b) : "memory");
}

// Lane-per-state init scatter (handles nonzero init messages; zeros -> no-op
// adds). Also fills bufs[0] with unary (race-free: only this kernel's atomics
// touch bufs[2], and nothing reads bufs[0] until the next kernel).
__global__ void scatter_init_lane(const float* __restrict__ m0,
                                  const float* __restrict__ m1,
                                  const int* __restrict__ eu,
                                  const int* __restrict__ ev,
                                  float* __restrict__ vb,
                                  float* __restrict__ fill,
                                  const float* __restrict__ unary,
                                  int nfill4, int E) {
    int t = blockIdx.x * blockDim.x + threadIdx.x;
    if (t < nfill4)
        reinterpret_cast<float4*>(fill)[t] =
            reinterpret_cast<const float4*>(unary)[t];
    int e = t >> 3, l = t & 7;
    if (e >= E) return;
    atomicAdd(vb + (size_t)eu[e] * 8 + l, m0[(size_t)e * 8 + l]);
    atomicAdd(vb + (size_t)ev[e] * 8 + l, m1[(size_t)e * 8 + l]);
}

// One BP step: 4 threads per edge, lane l owns states s0=2l, s1=2l+1.
// Grid-stride at exactly-full-wave size (148*6 blocks resident): removes the
// 0.52-wave tail that held R9 at 58% achieved occupancy.
// Also refills `fill` (next-next step's scatter target) with unary.
//  FIRST : read fp32 pairwise + init messages; emit q16 pairwise + packed msgs
//  !FIRST: read q16 pairwise + packed g_msg
//  LAST  : also emit calibrated factor beliefs (softmax over 64) to out_fb
template <bool FIRST, bool LAST>
__global__ void __launch_bounds__(256)
bp_lane4_kernel(const float* __restrict__ vb_cur,
                const float* __restrict__ pairwise,
                const int* __restrict__ eu,
                const int* __restrict__ ev,
                const float* __restrict__ im0,
                const float* __restrict__ im1,
                float* __restrict__ vb_next,
                float* __restrict__ fill,
                const float* __restrict__ unary,
                int nfill4,
                const unsigned char* __restrict__ fmask,
                float* __restrict__ out_fb, int E) {
    const int stride = gridDim.x * blockDim.x;
    // 4-lane group mask within the warp (stride % 4 == 0 keeps l invariant).
    const unsigned gm = 0xFu << (threadIdx.x & 28);
    const int l = threadIdx.x & 3;

    for (int t = blockIdx.x * blockDim.x + threadIdx.x; t < E * 4; t += stride) {
        // Fused reset of the (k+1)%3 buffer; fires only on the first pass
        // (stride > nfill4), safe: that buffer's last read was step k-1.
        if (t < nfill4)
            reinterpret_cast<float4*>(fill)[t] =
                reinterpret_cast<const float4*>(unary)[t];

        int e = t >> 2;
        int u = eu[e], v = ev[e];

        // Messages for owned states (m0 = msg to u, m1 = msg to v).
        float m00, m01, m10, m11;
        if (FIRST) {
            float2 a = *reinterpret_cast<const float2*>(im0 + (size_t)e * 8 + 2 * l);
            float2 b = *reinterpret_cast<const float2*>(im1 + (size_t)e * 8 + 2 * l);
            m00 = a.x; m01 = a.y; m10 = b.x; m11 = b.y;
        } else {
            float4 mm = *reinterpret_cast<const float4*>(g_msg + (size_t)e * 16 + l * 4);
            m00 = mm.x; m01 = mm.y; m10 = mm.z; m11 = mm.w;
        }
        float2 vbu = *reinterpret_cast<const float2*>(vb_cur + (size_t)u * 8 + 2 * l);
        float2 vbv = *reinterpret_cast<const float2*>(vb_cur + (size_t)v * 8 + 2 * l);
        float nu0 = vbu.x - m00, nu1 = vbu.y - m01;  // var->factor msgs
        float nv0 = vbv.x - m10, nv1 = vbv.y - m11;

        // Rows s0=2l, s1=2l+1 of this edge's 8x8 pairwise block.
        float row0[8], row1[8];
        if (FIRST) {
            const float* Pe = pairwise + (size_t)e * 64 + 2 * l * 8;  // 64B/lane
            float4 p0 = __ldg((const float4*)Pe);
            float4 p1 = __ldg((const float4*)(Pe + 4));
            float4 p2 = __ldg((const float4*)(Pe + 8));
            float4 p3 = __ldg((const float4*)(Pe + 12));
            float rf[16] = {p0.x, p0.y, p0.z, p0.w, p1.x, p1.y, p1.z, p1.w,
                            p2.x, p2.y, p2.z, p2.w, p3.x, p3.y, p3.z, p3.w};
            unsigned qw[8];
#pragma unroll
            for (int j = 0; j < 8; j++) {
                int a = __float2int_rn(fminf(fmaxf(rf[2 * j]     * Q_SCALE, -32767.f), 32767.f));
                int b = __float2int_rn(fminf(fmaxf(rf[2 * j + 1] * Q_SCALE, -32767.f), 32767.f));
                qw[j] = (unsigned)(a & 0xFFFF) | ((unsigned)b << 16);
            }
            short* qp = g_pw16 + (size_t)e * 64 + 16 * l;
            *reinterpret_cast<uint4*>(qp)     = make_uint4(qw[0], qw[1], qw[2], qw[3]);
            *reinterpret_cast<uint4*>(qp + 8) = make_uint4(qw[4], qw[5], qw[6], qw[7]);
            // Re-decode so all steps use identical (quantized) pairwise values.
#pragma unroll
            for (int j = 0; j < 8; j++) {
                short2 s2 = *reinterpret_cast<short2*>(&qw[j]);
                float x = (float)s2.x * Q_INV, y = (float)s2.y * Q_INV;
                if (j < 4) { row0[2 * j] = x; row0[2 * j + 1] = y; }
                else       { row1[2 * (j - 4)] = x; row1[2 * (j - 4) + 1] = y; }
            }
        } else {
            const short* qp = g_pw16 + (size_t)e * 64 + 16 * l;
            uint4 q0 = *reinterpret_cast<const uint4*>(qp);
            uint4 q1 = *reinterpret_cast<const uint4*>(qp + 8);
            unsigned qw[8] = {q0.x, q0.y, q0.z, q0.w, q1.x, q1.y, q1.z, q1.w};
#pragma unroll
            for (int j = 0; j < 4; j++) {
                short2 s2 = *reinterpret_cast<short2*>(&qw[j]);
                row0[2 * j]     = (float)s2.x * Q_INV;
                row0[2 * j + 1] = (float)s2.y * Q_INV;
                short2 s3 = *reinterpret_cast<short2*>(&qw[j + 4]);
                row1[2 * j]     = (float)s3.x * Q_INV;
                row1[2 * j + 1] = (float)s3.y * Q_INV;
            }
        }

        // All-gather nv across the 4-lane group (8 scalar shfls).
        float nvv[8];
#pragma unroll
        for (int j = 0; j < 4; j++) {
            nvv[2 * j]     = __shfl_sync(gm, nv0, j, 4);
            nvv[2 * j + 1] = __shfl_sync(gm, nv1, j, 4);
        }

        // Row maxes (messages to u, states s0/s1) — fully local.
        float nm00 = neg_inf(), nm01 = neg_inf();
        // Column partials: a[j] = max over owned rows of (P[r][j] + nu_r).
        float a[8];
#pragma unroll
        for (int j = 0; j < 8; j++) {
            nm00 = fmaxf(nm00, row0[j] + nvv[j]);
            nm01 = fmaxf(nm01, row1[j] + nvv[j]);
            a[j] = fmaxf(row0[j] + nu0, row1[j] + nu1);
        }

        // Reduce-scatter column maxes over 4 lanes (6 shfls): lane l ends with
        // columns 2l (a[0]) and 2l+1 (a[1]).
#pragma unroll
        for (int j = 0; j < 4; j++) {
            float send = (l & 2) ? a[j] : a[j + 4];
            float keep = (l & 2) ? a[j + 4] : a[j];
            float r = __shfl_xor_sync(gm, send, 2, 4);
            a[j] = fmaxf(keep, r);
        }
#pragma unroll
        for (int j = 0; j < 2; j++) {
            float send = (l & 1) ? a[j] : a[j + 2];
            float keep = (l & 1) ? a[j + 2] : a[j];
            float r = __shfl_xor_sync(gm, send, 1, 4);
            a[j] = fmaxf(keep, r);
        }
        float nm10 = a[0], nm11 = a[1];

        // Normalization maxes (2-stage butterflies, width 4).
        float mx0 = fmaxf(nm00, nm01);
        mx0 = fmaxf(mx0, __shfl_xor_sync(gm, mx0, 1, 4));
        mx0 = fmaxf(mx0, __shfl_xor_sync(gm, mx0, 2, 4));
        float mx1 = fmaxf(nm10, nm11);
        mx1 = fmaxf(mx1, __shfl_xor_sync(gm, mx1, 1, 4));
        mx1 = fmaxf(mx1, __shfl_xor_sync(gm, mx1, 2, 4));

        float o00 = 0.5f * m00 + 0.5f * (nm00 - mx0);
        float o01 = 0.5f * m01 + 0.5f * (nm01 - mx0);
        float o10 = 0.5f * m10 + 0.5f * (nm10 - mx1);
        float o11 = 0.5f * m11 + 0.5f * (nm11 - mx1);
        *reinterpret_cast<float4*>(g_msg + (size_t)e * 16 + l * 4) =
            make_float4(o00, o01, o10, o11);

        // Fused segment_sum for next step's var beliefs (vector RED).
        red_add_v2(vb_next + (size_t)u * 8 + 2 * l, o00, o01);
        red_add_v2(vb_next + (size_t)v * 8 + 2 * l, o10, o11);

        if (LAST) {
            // Factor beliefs rows s0,s1; mask; softmax over all 64.
            const unsigned char* fm = fmask + (size_t)e * 64 + 16 * l;
            uint4 mq = *reinterpret_cast<const uint4*>(fm);
            unsigned mw[4] = {mq.x, mq.y, mq.z, mq.w};
            float fb0[8], fb1[8];
#pragma unroll
            for (int j = 0; j < 8; j++) {
                float x0 = row0[j] + nu0 + nvv[j];
                float x1 = row1[j] + nu1 + nvv[j];
                if ((mw[j >> 2] >> ((j & 3) * 8)) & 0xFFu) x0 = neg_inf();
                if ((mw[2 + (j >> 2)] >> ((j & 3) * 8)) & 0xFFu) x1 = neg_inf();
                fb0[j] = x0; fb1[j] = x1;
            }
            float gmax = neg_inf();
#pragma unroll
            for (int j = 0; j < 8; j++) gmax = fmaxf(gmax, fmaxf(fb0[j], fb1[j]));
            gmax = fmaxf(gmax, __shfl_xor_sync(gm, gmax, 1, 4));
            gmax = fmaxf(gmax, __shfl_xor_sync(gm, gmax, 2, 4));
            float s = 0.f;
#pragma unroll
            for (int j = 0; j < 8; j++) {
                fb0[j] = __expf(fb0[j] - gmax);
                fb1[j] = __expf(fb1[j] - gmax);
                s += fb0[j] + fb1[j];
            }
            s += __shfl_xor_sync(gm, s, 1, 4);
            s += __shfl_xor_sync(gm, s, 2, 4);
            float inv = 1.0f / s;
            float* op = out_fb + (size_t)e * 64 + 16 * l;
            stg_cs4(op,      make_float4(fb0[0] * inv, fb0[1] * inv, fb0[2] * inv, fb0[3] * inv));
            stg_cs4(op + 4,  make_float4(fb0[4] * inv, fb0[5] * inv, fb0[6] * inv, fb0[7] * inv));
            stg_cs4(op + 8,  make_float4(fb1[0] * inv, fb1[1] * inv, fb1[2] * inv, fb1[3] * inv));
            stg_cs4(op + 12, make_float4(fb1[4] * inv, fb1[5] * inv, fb1[6] * inv, fb1[7] * inv));
        }
    }
}

// Calibrated var beliefs: masked softmax over S=8, one thread per variable.
__global__ void vb_out_kernel(const float* __restrict__ vb,
                              const unsigned char* __restrict__ vmask,
                              float* __restrict__ out, int V) {
    int x = blockIdx.x * blockDim.x + threadIdx.x;
    if (x >= V) return;
    float4 a = *reinterpret_cast<const float4*>(vb + (size_t)x * 8);
    float4 b = *reinterpret_cast<const float4*>(vb + (size_t)x * 8 + 4);
    float r[8] = {a.x, a.y, a.z, a.w, b.x, b.y, b.z, b.w};
    uint2 mq = *reinterpret_cast<const uint2*>(vmask + (size_t)x * 8);
    unsigned mw[2] = {mq.x, mq.y};
#pragma unroll
    for (int q = 0; q < 2; q++)
#pragma unroll
        for (int bb = 0; bb < 4; bb++)
            if ((mw[q] >> (8 * bb)) & 0xFFu) r[q * 4 + bb] = neg_inf();
    float m = neg_inf();
#pragma unroll
    for (int i = 0; i < 8; i++) m = fmaxf(m, r[i]);
    float s = 0.f;
#pragma unroll
    for (int i = 0; i < 8; i++) {
        r[i] = __expf(r[i] - m);
        s += r[i];
    }
    float inv = 1.0f / s;
    float* op = out + (size_t)x * 8;
    stg_cs4(op,     make_float4(r[0] * inv, r[1] * inv, r[2] * inv, r[3] * inv));
    stg_cs4(op + 4, make_float4(r[4] * inv, r[5] * inv, r[6] * inv, r[7] * inv));
}

extern "C" void kernel_launch(void* const* d_in, const int* in_sizes, int n_in,
                              void* d_out, int out_size) {
    const float* unary         = (const float*)d_in[0];
    const float* pairwise      = (const float*)d_in[1];
    const float* init_m        = (const float*)d_in[2];
    const int* eidx            = (const int*)d_in[3];
    const unsigned char* vmask = (const unsigned char*)d_in[4];
    const unsigned char* fmask = (const unsigned char*)d_in[5];

    int V = in_sizes[0] / 8;
    int E = in_sizes[1] / 64;
    const int* eu = eidx;
    const int* ev = eidx + E;
    const float* im0 = init_m;
    const float* im1 = init_m + (size_t)E * 8;

    float* out_vb = (float*)d_out;
    float* out_fb = out_vb + (size_t)V * 8;

    float* vbb_base;
    cudaGetSymbolAddress((void**)&vbb_base, g_vb);
    float* bufs[3] = {vbb_base,
                      vbb_base + (size_t)MAX_V * 8,
                      vbb_base + (size_t)2 * MAX_V * 8};

    size_t vbb = (size_t)V * 8 * sizeof(float);
    int nfill4 = V * 2;  // V*8 floats as float4
    int threads = 256;
    int blocks8 = (E * 8 + threads - 1) / threads;
    // Exactly-full-wave grid: 6 blocks/SM resident at 40 regs, 148 SMs.
    int wave_blocks = 148 * 6;

    // Step 0 reads bufs[2] = unary + segment_sum(init msgs);
    // scatters into bufs[0] (filled with unary inside scatter_init).
    cudaMemcpyAsync(bufs[2], unary, vbb, cudaMemcpyDeviceToDevice, 0);
    scatter_init_lane<<<blocks8, threads>>>(im0, im1, eu, ev, bufs[2],
                                            bufs[0], unary, nfill4, E);

    // 7 steps: step k reads bufs[(k+2)%3], writes bufs[k%3], and refills
    // bufs[(k+1)%3] with unary for step k+1 (safe: last read at step k-1).
    bp_lane4_kernel<true, false><<<wave_blocks, threads>>>(
        bufs[2], pairwise, eu, ev, im0, im1, bufs[0],
        bufs[1], unary, nfill4, fmask, out_fb, E);
    for (int k = 1; k < 7; k++) {
        float* rd = bufs[(k + 2) % 3];
        float* wr = bufs[k % 3];
        float* fl = bufs[(k + 1) % 3];
        if (k < 6)
            bp_lane4_kernel<false, false><<<wave_blocks, threads>>>(
                rd, pairwise, eu, ev, nullptr, nullptr, wr,
                fl, unary, nfill4, fmask, out_fb, E);
        else
            bp_lane4_kernel<false, true><<<wave_blocks, threads>>>(
                rd, pairwise, eu, ev, nullptr, nullptr, wr,
                fl, unary, 0, fmask, out_fb, E);
    }

    // Final var beliefs live in bufs[6%3] = bufs[0].
    vb_out_kernel<<<(V + 127) / 128, 128>>>(bufs[0], vmask, out_vb, V);
}

// round 11
// speedup vs baseline: 1.1532x; 1.1532x over previous
#include <cuda_runtime.h>

#define MAX_V 50000
#define MAX_E 200000

// Scratch (device globals — no allocation allowed in kernel_launch).
// 3 rotating var-belief buffers: at step k, read (k+2)%3, write k%3, and
// refill (k+1)%3 with unary for step k+1 (its last reader was step k-1).
__device__ __align__(16) float g_vb[3][MAX_V * 8];
// Messages, interleaved per 4-lane layout: edge e, lane l (states 2l,2l+1)
// holds float4 {m0[2l], m0[2l+1], m1[2l], m1[2l+1]} at g_msg[e*16 + l*4].
__device__ __align__(16) float g_msg[MAX_E * 16];
// int16-quantized pairwise (scale 4096): halves the dominant stream.
__device__ __align__(16) short g_pw16[MAX_E * 64];

#define Q_SCALE 4096.0f
#define Q_INV   2.44140625e-4f

__device__ __forceinline__ float neg_inf() { return __int_as_float(0xff800000); }

// Streaming store (outputs: written once, never re-read — don't pollute L2).
__device__ __forceinline__ void stg_cs4(float* p, float4 v) {
    asm volatile("st.global.cs.v4.f32 [%0], {%1,%2,%3,%4};"
                 :: "l"(p), "f"(v.x), "f"(v.y), "f"(v.z), "f"(v.w));
}
// Vector float2 reduction (sm_90+): one RED issue for two states.
__device__ __forceinline__ void red_add_v2(float* p, float a, float b) {
    asm volatile("red.global.add.v2.f32 [%0], {%1, %2};"
                 :: "l"(p), "f"(a), "f"(b) : "memory");
}

// Lane-per-state init scatter (handles nonzero init messages; zeros -> no-op
// adds). Also fills bufs[0] with unary (race-free: only this kernel's atomics
// touch bufs[2], and nothing reads bufs[0] until the next kernel).
__global__ void scatter_init_lane(const float* __restrict__ m0,
                                  const float* __restrict__ m1,
                                  const int* __restrict__ eu,
                                  const int* __restrict__ ev,
                                  float* __restrict__ vb,
                                  float* __restrict__ fill,
                                  const float* __restrict__ unary,
                                  int nfill4, int E) {
    int t = blockIdx.x * blockDim.x + threadIdx.x;
    if (t < nfill4)
        reinterpret_cast<float4*>(fill)[t] =
            reinterpret_cast<const float4*>(unary)[t];
    int e = t >> 3, l = t & 7;
    if (e >= E) return;
    atomicAdd(vb + (size_t)eu[e] * 8 + l, m0[(size_t)e * 8 + l]);
    atomicAdd(vb + (size_t)ev[e] * 8 + l, m1[(size_t)e * 8 + l]);
}

// One BP step: 4 threads per edge, lane l owns states s0=2l, s1=2l+1.
// Flat mapping (R10's grid-stride loop pushed regs 40->48 and cost a block/SM).
// Block=128 -> 12 blocks/SM at ~40 regs; grid 12500 = 7.04 waves (tiny tail).
// Also refills `fill` (next-next step's scatter target) with unary.
//  FIRST : read fp32 pairwise + init messages; emit q16 pairwise + packed msgs
//  !FIRST: read q16 pairwise + packed g_msg
//  LAST  : also emit calibrated factor beliefs (softmax over 64) to out_fb
template <bool FIRST, bool LAST>
__global__ void __launch_bounds__(128)
bp_lane4_kernel(const float* __restrict__ vb_cur,
                const float* __restrict__ pairwise,
                const int* __restrict__ eu,
                const int* __restrict__ ev,
                const float* __restrict__ im0,
                const float* __restrict__ im1,
                float* __restrict__ vb_next,
                float* __restrict__ fill,
                const float* __restrict__ unary,
                int nfill4,
                const unsigned char* __restrict__ fmask,
                float* __restrict__ out_fb, int E) {
    int t = blockIdx.x * blockDim.x + threadIdx.x;

    // Fused reset of the (k+1)%3 buffer (safe: last read at step k-1).
    if (t < nfill4)
        reinterpret_cast<float4*>(fill)[t] =
            reinterpret_cast<const float4*>(unary)[t];

    int e = t >> 2, l = t & 3;
    if (e >= E) return;
    // 4-lane group mask within the warp.
    unsigned gm = 0xFu << (threadIdx.x & 28);

    int u = eu[e], v = ev[e];

    // Messages for owned states (m0 = msg to u, m1 = msg to v).
    float m00, m01, m10, m11;
    if (FIRST) {
        float2 a = *reinterpret_cast<const float2*>(im0 + (size_t)e * 8 + 2 * l);
        float2 b = *reinterpret_cast<const float2*>(im1 + (size_t)e * 8 + 2 * l);
        m00 = a.x; m01 = a.y; m10 = b.x; m11 = b.y;
    } else {
        float4 mm = *reinterpret_cast<const float4*>(g_msg + (size_t)e * 16 + l * 4);
        m00 = mm.x; m01 = mm.y; m10 = mm.z; m11 = mm.w;
    }
    float2 vbu = *reinterpret_cast<const float2*>(vb_cur + (size_t)u * 8 + 2 * l);
    float2 vbv = *reinterpret_cast<const float2*>(vb_cur + (size_t)v * 8 + 2 * l);
    float nu0 = vbu.x - m00, nu1 = vbu.y - m01;   // var->factor msgs, states 2l,2l+1
    float nv0 = vbv.x - m10, nv1 = vbv.y - m11;

    // Rows s0=2l, s1=2l+1 of this edge's 8x8 pairwise block.
    float row0[8], row1[8];
    if (FIRST) {
        const float* Pe = pairwise + (size_t)e * 64 + 2 * l * 8;  // 64B/lane
        float4 p0 = __ldg((const float4*)Pe);
        float4 p1 = __ldg((const float4*)(Pe + 4));
        float4 p2 = __ldg((const float4*)(Pe + 8));
        float4 p3 = __ldg((const float4*)(Pe + 12));
        float rf[16] = {p0.x, p0.y, p0.z, p0.w, p1.x, p1.y, p1.z, p1.w,
                        p2.x, p2.y, p2.z, p2.w, p3.x, p3.y, p3.z, p3.w};
        unsigned qw[8];
#pragma unroll
        for (int j = 0; j < 8; j++) {
            int a = __float2int_rn(fminf(fmaxf(rf[2 * j]     * Q_SCALE, -32767.f), 32767.f));
            int b = __float2int_rn(fminf(fmaxf(rf[2 * j + 1] * Q_SCALE, -32767.f), 32767.f));
            qw[j] = (unsigned)(a & 0xFFFF) | ((unsigned)b << 16);
        }
        short* qp = g_pw16 + (size_t)e * 64 + 16 * l;
        *reinterpret_cast<uint4*>(qp)     = make_uint4(qw[0], qw[1], qw[2], qw[3]);
        *reinterpret_cast<uint4*>(qp + 8) = make_uint4(qw[4], qw[5], qw[6], qw[7]);
        // Re-decode so all steps use identical (quantized) pairwise values.
#pragma unroll
        for (int j = 0; j < 8; j++) {
            short2 s2 = *reinterpret_cast<short2*>(&qw[j]);
            float x = (float)s2.x * Q_INV, y = (float)s2.y * Q_INV;
            if (j < 4) { row0[2 * j] = x; row0[2 * j + 1] = y; }
            else       { row1[2 * (j - 4)] = x; row1[2 * (j - 4) + 1] = y; }
        }
    } else {
        const short* qp = g_pw16 + (size_t)e * 64 + 16 * l;
        uint4 q0 = *reinterpret_cast<const uint4*>(qp);
        uint4 q1 = *reinterpret_cast<const uint4*>(qp + 8);
        unsigned qw[8] = {q0.x, q0.y, q0.z, q0.w, q1.x, q1.y, q1.z, q1.w};
#pragma unroll
        for (int j = 0; j < 4; j++) {
            short2 s2 = *reinterpret_cast<short2*>(&qw[j]);
            row0[2 * j]     = (float)s2.x * Q_INV;
            row0[2 * j + 1] = (float)s2.y * Q_INV;
            short2 s3 = *reinterpret_cast<short2*>(&qw[j + 4]);
            row1[2 * j]     = (float)s3.x * Q_INV;
            row1[2 * j + 1] = (float)s3.y * Q_INV;
        }
    }

    // All-gather nv across the 4-lane group (8 scalar shfls).
    float nvv[8];
#pragma unroll
    for (int j = 0; j < 4; j++) {
        nvv[2 * j]     = __shfl_sync(gm, nv0, j, 4);
        nvv[2 * j + 1] = __shfl_sync(gm, nv1, j, 4);
    }

    // Row maxes (messages to u, states s0/s1) — fully local.
    float nm00 = neg_inf(), nm01 = neg_inf();
    // Column partials: a[j] = max over owned rows of (P[r][j] + nu_r).
    float a[8];
#pragma unroll
    for (int j = 0; j < 8; j++) {
        nm00 = fmaxf(nm00, row0[j] + nvv[j]);
        nm01 = fmaxf(nm01, row1[j] + nvv[j]);
        a[j] = fmaxf(row0[j] + nu0, row1[j] + nu1);
    }

    // Reduce-scatter column maxes over 4 lanes (6 shfls): lane l ends with
    // columns 2l (a[0]) and 2l+1 (a[1]).
#pragma unroll
    for (int j = 0; j < 4; j++) {
        float send = (l & 2) ? a[j] : a[j + 4];
        float keep = (l & 2) ? a[j + 4] : a[j];
        float r = __shfl_xor_sync(gm, send, 2, 4);
        a[j] = fmaxf(keep, r);
    }
#pragma unroll
    for (int j = 0; j < 2; j++) {
        float send = (l & 1) ? a[j] : a[j + 2];
        float keep = (l & 1) ? a[j + 2] : a[j];
        float r = __shfl_xor_sync(gm, send, 1, 4);
        a[j] = fmaxf(keep, r);
    }
    float nm10 = a[0], nm11 = a[1];

    // Normalization maxes (2-stage butterflies, width 4).
    float mx0 = fmaxf(nm00, nm01);
    mx0 = fmaxf(mx0, __shfl_xor_sync(gm, mx0, 1, 4));
    mx0 = fmaxf(mx0, __shfl_xor_sync(gm, mx0, 2, 4));
    float mx1 = fmaxf(nm10, nm11);
    mx1 = fmaxf(mx1, __shfl_xor_sync(gm, mx1, 1, 4));
    mx1 = fmaxf(mx1, __shfl_xor_sync(gm, mx1, 2, 4));

    float o00 = 0.5f * m00 + 0.5f * (nm00 - mx0);
    float o01 = 0.5f * m01 + 0.5f * (nm01 - mx0);
    float o10 = 0.5f * m10 + 0.5f * (nm10 - mx1);
    float o11 = 0.5f * m11 + 0.5f * (nm11 - mx1);
    *reinterpret_cast<float4*>(g_msg + (size_t)e * 16 + l * 4) =
        make_float4(o00, o01, o10, o11);

    // Fused segment_sum for next step's var beliefs (vector RED).
    red_add_v2(vb_next + (size_t)u * 8 + 2 * l, o00, o01);
    red_add_v2(vb_next + (size_t)v * 8 + 2 * l, o10, o11);

    if (LAST) {
        // Factor beliefs rows s0,s1; mask; softmax over all 64.
        const unsigned char* fm = fmask + (size_t)e * 64 + 16 * l;
        uint4 mq = *reinterpret_cast<const uint4*>(fm);
        unsigned mw[4] = {mq.x, mq.y, mq.z, mq.w};
        float fb0[8], fb1[8];
#pragma unroll
        for (int j = 0; j < 8; j++) {
            float x0 = row0[j] + nu0 + nvv[j];
            float x1 = row1[j] + nu1 + nvv[j];
            if ((mw[j >> 2] >> ((j & 3) * 8)) & 0xFFu) x0 = neg_inf();
            if ((mw[2 + (j >> 2)] >> ((j & 3) * 8)) & 0xFFu) x1 = neg_inf();
            fb0[j] = x0; fb1[j] = x1;
        }
        float gmax = neg_inf();
#pragma unroll
        for (int j = 0; j < 8; j++) gmax = fmaxf(gmax, fmaxf(fb0[j], fb1[j]));
        gmax = fmaxf(gmax, __shfl_xor_sync(gm, gmax, 1, 4));
        gmax = fmaxf(gmax, __shfl_xor_sync(gm, gmax, 2, 4));
        float s = 0.f;
#pragma unroll
        for (int j = 0; j < 8; j++) {
            fb0[j] = __expf(fb0[j] - gmax);
            fb1[j] = __expf(fb1[j] - gmax);
            s += fb0[j] + fb1[j];
        }
        s += __shfl_xor_sync(gm, s, 1, 4);
        s += __shfl_xor_sync(gm, s, 2, 4);
        float inv = 1.0f / s;
        float* op = out_fb + (size_t)e * 64 + 16 * l;
        stg_cs4(op,      make_float4(fb0[0] * inv, fb0[1] * inv, fb0[2] * inv, fb0[3] * inv));
        stg_cs4(op + 4,  make_float4(fb0[4] * inv, fb0[5] * inv, fb0[6] * inv, fb0[7] * inv));
        stg_cs4(op + 8,  make_float4(fb1[0] * inv, fb1[1] * inv, fb1[2] * inv, fb1[3] * inv));
        stg_cs4(op + 12, make_float4(fb1[4] * inv, fb1[5] * inv, fb1[6] * inv, fb1[7] * inv));
    }
}

// Calibrated var beliefs: masked softmax over S=8, one thread per variable.
__global__ void vb_out_kernel(const float* __restrict__ vb,
                              const unsigned char* __restrict__ vmask,
                              float* __restrict__ out, int V) {
    int x = blockIdx.x * blockDim.x + threadIdx.x;
    if (x >= V) return;
    float4 a = *reinterpret_cast<const float4*>(vb + (size_t)x * 8);
    float4 b = *reinterpret_cast<const float4*>(vb + (size_t)x * 8 + 4);
    float r[8] = {a.x, a.y, a.z, a.w, b.x, b.y, b.z, b.w};
    uint2 mq = *reinterpret_cast<const uint2*>(vmask + (size_t)x * 8);
    unsigned mw[2] = {mq.x, mq.y};
#pragma unroll
    for (int q = 0; q < 2; q++)
#pragma unroll
        for (int bb = 0; bb < 4; bb++)
            if ((mw[q] >> (8 * bb)) & 0xFFu) r[q * 4 + bb] = neg_inf();
    float m = neg_inf();
#pragma unroll
    for (int i = 0; i < 8; i++) m = fmaxf(m, r[i]);
    float s = 0.f;
#pragma unroll
    for (int i = 0; i < 8; i++) {
        r[i] = __expf(r[i] - m);
        s += r[i];
    }
    float inv = 1.0f / s;
    float* op = out + (size_t)x * 8;
    stg_cs4(op,     make_float4(r[0] * inv, r[1] * inv, r[2] * inv, r[3] * inv));
    stg_cs4(op + 4, make_float4(r[4] * inv, r[5] * inv, r[6] * inv, r[7] * inv));
}

extern "C" void kernel_launch(void* const* d_in, const int* in_sizes, int n_in,
                              void* d_out, int out_size) {
    const float* unary         = (const float*)d_in[0];
    const float* pairwise      = (const float*)d_in[1];
    const float* init_m        = (const float*)d_in[2];
    const int* eidx            = (const int*)d_in[3];
    const unsigned char* vmask = (const unsigned char*)d_in[4];
    const unsigned char* fmask = (const unsigned char*)d_in[5];

    int V = in_sizes[0] / 8;
    int E = in_sizes[1] / 64;
    const int* eu = eidx;
    const int* ev = eidx + E;
    const float* im0 = init_m;
    const float* im1 = init_m + (size_t)E * 8;

    float* out_vb = (float*)d_out;
    float* out_fb = out_vb + (size_t)V * 8;

    float* vbb_base;
    cudaGetSymbolAddress((void**)&vbb_base, g_vb);
    float* bufs[3] = {vbb_base,
                      vbb_base + (size_t)MAX_V * 8,
                      vbb_base + (size_t)2 * MAX_V * 8};

    size_t vbb = (size_t)V * 8 * sizeof(float);
    int nfill4 = V * 2;  // V*8 floats as float4
    int blocks8 = (E * 8 + 255) / 256;
    // Step kernel: block=128 for finer wave granularity (12 blocks/SM @ ~40 regs,
    // 12500 blocks = 7.04 waves -> near-zero tail).
    int sthreads = 128;
    int sblocks = (E * 4 + sthreads - 1) / sthreads;

    // Step 0 reads bufs[2] = unary + segment_sum(init msgs);
    // scatters into bufs[0] (filled with unary inside scatter_init).
    cudaMemcpyAsync(bufs[2], unary, vbb, cudaMemcpyDeviceToDevice, 0);
    scatter_init_lane<<<blocks8, 256>>>(im0, im1, eu, ev, bufs[2],
                                        bufs[0], unary, nfill4, E);

    // 7 steps: step k reads bufs[(k+2)%3], writes bufs[k%3], and refills
    // bufs[(k+1)%3] with unary for step k+1 (safe: last read at step k-1).
    bp_lane4_kernel<true, false><<<sblocks, sthreads>>>(
        bufs[2], pairwise, eu, ev, im0, im1, bufs[0],
        bufs[1], unary, nfill4, fmask, out_fb, E);
    for (int k = 1; k < 7; k++) {
        float* rd = bufs[(k + 2) % 3];
        float* wr = bufs[k % 3];
        float* fl = bufs[(k + 1) % 3];
        if (k < 6)
            bp_lane4_kernel<false, false><<<sblocks, sthreads>>>(
                rd, pairwise, eu, ev, nullptr, nullptr, wr,
                fl, unary, nfill4, fmask, out_fb, E);
        else
            bp_lane4_kernel<false, true><<<sblocks, sthreads>>>(
                rd, pairwise, eu, ev, nullptr, nullptr, wr,
                fl, unary, 0, fmask, out_fb, E);
    }

    // Final var beliefs live in bufs[6%3] = bufs[0].
    vb_out_kernel<<<(V + 127) / 128, 128>>>(bufs[0], vmask, out_vb, V);
}